// round 8
// baseline (speedup 1.0000x reference)
#include <cuda_runtime.h>
#include <math.h>

#define Bn 16
#define Nn 1000
#define En 16000
#define NT 16000          /* Bn*Nn total nodes  */
#define EBASE 256000      /* Bn*En edges before self loops */
#define ETOT 272000       /* + NT self loops */
#define TWOE 32000
#define HALFB 8
#define NLOW 8000         /* dsts 0..7999 have only their self loop (structural) */

#define H1n 8
#define F1 1024           /* H1*C1 */
#define EMBn 64
#define HIDn 128
#define BCAP 96           /* bucket capacity per heavy dst */

#define NCHUNK 400
#define CK 160            /* 400*160 = 64000 */

#define NBLK 296
#define NTHR 256
#define NTOT (NBLK * NTHR)   /* 75776 threads */

// ------------------------- scratch (static, no allocs) -------------------------
__device__ __align__(16) float4 g_xf[NT];
__device__ float g_psrc[24];
__device__ float g_pdst[24];
__device__ int   g_cursor[NT];                       // zero at load; re-zeroed in mlp1 phase
__device__ int   g_bucket[NT * BCAP];
__device__ float g_s[NT * 24];
__device__ __align__(16) float g_h2[NT * EMBn];
__device__ float g_a2s[NT];
__device__ float g_a2d[NT];
__device__ __align__(16) float g_x2t[64000 * 16];
__device__ float g_part[NCHUNK * 16 * HIDn];
__device__ float g_y1[16 * HIDn];
__device__ float g_y2[16 * HIDn];
__device__ unsigned g_bar_count;
__device__ unsigned g_bar_gen;

// ------------------------- helpers -------------------------
__device__ __forceinline__ void edge_sd(int e, const int* __restrict__ EI, int& src, int& dst) {
    if (e < EBASE) {
        int b   = e / TWOE;
        int rem = e - b * TWOE;
        src = EI[b * TWOE + rem] + b * Nn;
        int b2 = b + HALFB;
        dst = EI[b2 * TWOE + rem] + b2 * Nn;
    } else {
        src = dst = e - EBASE;
    }
}

__device__ __forceinline__ float warp_sum(float v) {
    #pragma unroll
    for (int o = 16; o > 0; o >>= 1) v += __shfl_xor_sync(0xffffffffu, v, o);
    return v;
}
__device__ __forceinline__ float leaky(float v) { return v > 0.f ? v : 0.2f * v; }
__device__ __forceinline__ float elu(float v)   { return v > 0.f ? v : (__expf(v) - 1.0f); }

__device__ __forceinline__ float2 ffma2(float2 a, float2 b, float2 c) {
    unsigned long long A = *reinterpret_cast<unsigned long long*>(&a);
    unsigned long long B = *reinterpret_cast<unsigned long long*>(&b);
    unsigned long long C = *reinterpret_cast<unsigned long long*>(&c);
    unsigned long long D;
    asm("fma.rn.f32x2 %0, %1, %2, %3;" : "=l"(D) : "l"(A), "l"(B), "l"(C));
    return *reinterpret_cast<float2*>(&D);
}

// grid barrier: generation counter + gpu-scope fences (CCTL.IVALL flushes L1D
// so post-barrier reads observe other SMs' writes within this launch).
__device__ __forceinline__ void gbar() {
    __threadfence();               // my writes -> visible
    __syncthreads();
    if (threadIdx.x == 0) {
        unsigned gen = *(volatile unsigned*)&g_bar_gen;
        if (atomicAdd(&g_bar_count, 1u) == NBLK - 1) {
            g_bar_count = 0;
            __threadfence();
            atomicExch(&g_bar_gen, gen + 1);
        } else {
            while (*(volatile unsigned*)&g_bar_gen == gen) { __nanosleep(32); }
        }
    }
    __syncthreads();
    __threadfence();               // invalidate L1 -> fresh reads
}

// ------------------------- shared pool overlays -------------------------
struct FgemmS {                    // 73,728 B (same footprint as R6 fgemm)
    float2 sAt[2][32][68];         // 34,816
    float  sB[2][32][EMBn];        // 16,384
    float  sW1[3 * F1];            // 12,288
    float  sB1[F1];                //  4,096
    float  sS[64 * 24];            //  6,144
};
struct Conv2S {
    float wbuf[8][BCAP];
    int   ibuf[8][BCAP];
};
struct Mlp1S {
    float sx[2][CK * 16];          // 20,480
};
struct TailS {
    float ys[16 * HIDn];           // 8,192
};

// ------------------------- the one kernel -------------------------
__global__ __launch_bounds__(NTHR, 2) void fused_kernel(
    const float* __restrict__ actions, const float* __restrict__ nodef,
    const int* __restrict__ EI,
    const float* __restrict__ W1, const float* __restrict__ as1,
    const float* __restrict__ ad1, const float* __restrict__ b1,
    const float* __restrict__ W2, const float* __restrict__ as2,
    const float* __restrict__ ad2, const float* __restrict__ b2,
    const float* __restrict__ mw1, const float* __restrict__ mb1,
    const float* __restrict__ mw2, const float* __restrict__ mb2,
    const float* __restrict__ ow,  const float* __restrict__ ob,
    float* __restrict__ out)
{
    __shared__ __align__(16) char pool[sizeof(FgemmS)];
    int tid = threadIdx.x;
    int bid = blockIdx.x;
    int gidx = bid * NTHR + tid;

    // ================= phase 1: node features + projections + bucket scatter =================
    if (gidx < NT) {
        float ax = actions[gidx * 2 + 0];
        float ay = actions[gidx * 2 + 1];
        float nf = nodef[gidx];
        g_xf[gidx] = make_float4(ax, ay, nf, 0.f);
    } else if (gidx < NT + 48) {
        int t = gidx - NT;
        int which = t / 24;
        int r = t % 24;
        int k = r / 8, h = r % 8;
        const float* att = which ? ad1 : as1;
        float s = 0.f;
        for (int c = 0; c < 128; c++)
            s += W1[k * F1 + h * 128 + c] * att[h * 128 + c];
        (which ? g_pdst : g_psrc)[k * 8 + h] = s;
    }
    #pragma unroll
    for (int q = 0; q < 4; q++) {
        int e = gidx * 4 + q;
        if (e < ETOT) {
            int src, dst;
            edge_sd(e, EI, src, dst);
            if (dst >= NLOW) {                 // low dsts only have their self loop
                int pos = atomicAdd(&g_cursor[dst], 1);
                g_bucket[dst * BCAP + pos] = src;
            }
        }
    }
    gbar();

    // ================= phase 2: conv1 attention =================
    // low half (d<8000): s = x[d] exactly (softmax of single self loop)
    // heavy half: thread per (d, head), serial edge walk
    for (int i = gidx; i < 128000; i += NTOT) {
        if (i < 64000) {
            int d = i >> 3, h = i & 7;
            float4 x = g_xf[d];
            float* sp = g_s + d * 24 + h * 3;
            sp[0] = x.x; sp[1] = x.y; sp[2] = x.z;
        } else {
            int i2 = i - 64000;
            int d = NLOW + (i2 >> 3), h = i2 & 7;
            float4 xd = g_xf[d];
            float p0 = g_psrc[h], p1 = g_psrc[8 + h], p2 = g_psrc[16 + h];
            float q0 = g_pdst[h], q1 = g_pdst[8 + h], q2 = g_pdst[16 + h];
            float adv = fmaf(xd.x, q0, fmaf(xd.y, q1, xd.z * q2));
            int deg = g_cursor[d];
            const int* bkt = g_bucket + d * BCAP;
            float se = 0.f, sx = 0.f, sy = 0.f, sz = 0.f;
            for (int e = 0; e < deg; e++) {
                int s = bkt[e];
                float4 x = g_xf[s];
                float a = fmaf(x.x, p0, fmaf(x.y, p1, x.z * p2)) + adv;
                float ea = __expf(leaky(a));
                se += ea;
                sx = fmaf(ea, x.x, sx);
                sy = fmaf(ea, x.y, sy);
                sz = fmaf(ea, x.z, sz);
            }
            float inv = 1.0f / se;
            float* sp = g_s + d * 24 + h * 3;
            sp[0] = sx * inv; sp[1] = sy * inv; sp[2] = sz * inv;
        }
    }
    gbar();

    // ================= phase 3: fused expand + GEMM + attn2 epilogue =================
    if (bid < 250) {
        FgemmS* fs = (FgemmS*)pool;
        int row0 = bid * 64;
        for (int i = tid; i < 3 * F1; i += NTHR) fs->sW1[i] = W1[i];
        for (int i = tid; i < F1; i += NTHR)     fs->sB1[i] = b1[i];
        for (int i = tid; i < 64 * 24; i += NTHR) fs->sS[i] = g_s[row0 * 24 + i];
        __syncthreads();

        int tx = tid % 16, ty = tid / 16;
        int br = tid & 63;
        int bc0 = (tid >> 6) * 8;

        float2 acc[4][2];
        #pragma unroll
        for (int i = 0; i < 4; i++) { acc[i][0] = make_float2(0.f, 0.f); acc[i][1] = make_float2(0.f, 0.f); }

        #define BUILD_CHUNK(cidx, buf)                                                        \
        {                                                                                     \
            int kc_ = (cidx) * 32;                                                            \
            int h_ = kc_ >> 7;                                                                \
            float s0 = fs->sS[br * 24 + h_ * 3 + 0];                                          \
            float s1 = fs->sS[br * 24 + h_ * 3 + 1];                                          \
            float s2 = fs->sS[br * 24 + h_ * 3 + 2];                                          \
            int cb = kc_ + bc0;                                                               \
            float4 w0a = *(const float4*)&fs->sW1[cb];                                        \
            float4 w0b = *(const float4*)&fs->sW1[cb + 4];                                    \
            float4 w1a = *(const float4*)&fs->sW1[F1 + cb];                                   \
            float4 w1b = *(const float4*)&fs->sW1[F1 + cb + 4];                               \
            float4 w2a = *(const float4*)&fs->sW1[2 * F1 + cb];                               \
            float4 w2b = *(const float4*)&fs->sW1[2 * F1 + cb + 4];                           \
            float4 ba  = *(const float4*)&fs->sB1[cb];                                        \
            float4 bbv = *(const float4*)&fs->sB1[cb + 4];                                    \
            float v0 = elu(fmaf(s0, w0a.x, fmaf(s1, w1a.x, fmaf(s2, w2a.x, ba.x))));          \
            float v1 = elu(fmaf(s0, w0a.y, fmaf(s1, w1a.y, fmaf(s2, w2a.y, ba.y))));          \
            float v2 = elu(fmaf(s0, w0a.z, fmaf(s1, w1a.z, fmaf(s2, w2a.z, ba.z))));          \
            float v3 = elu(fmaf(s0, w0a.w, fmaf(s1, w1a.w, fmaf(s2, w2a.w, ba.w))));          \
            float v4 = elu(fmaf(s0, w0b.x, fmaf(s1, w1b.x, fmaf(s2, w2b.x, bbv.x))));         \
            float v5 = elu(fmaf(s0, w0b.y, fmaf(s1, w1b.y, fmaf(s2, w2b.y, bbv.y))));         \
            float v6 = elu(fmaf(s0, w0b.z, fmaf(s1, w1b.z, fmaf(s2, w2b.z, bbv.z))));         \
            float v7 = elu(fmaf(s0, w0b.w, fmaf(s1, w1b.w, fmaf(s2, w2b.w, bbv.w))));         \
            fs->sAt[buf][bc0 + 0][br] = make_float2(v0, v0);                                  \
            fs->sAt[buf][bc0 + 1][br] = make_float2(v1, v1);                                  \
            fs->sAt[buf][bc0 + 2][br] = make_float2(v2, v2);                                  \
            fs->sAt[buf][bc0 + 3][br] = make_float2(v3, v3);                                  \
            fs->sAt[buf][bc0 + 4][br] = make_float2(v4, v4);                                  \
            fs->sAt[buf][bc0 + 5][br] = make_float2(v5, v5);                                  \
            fs->sAt[buf][bc0 + 6][br] = make_float2(v6, v6);                                  \
            fs->sAt[buf][bc0 + 7][br] = make_float2(v7, v7);                                  \
            int q0_ = tid * 2;                                                                \
            int k0_ = q0_ >> 4, c40 = (q0_ & 15) * 4;                                         \
            *(float4*)&fs->sB[buf][k0_][c40] = *(const float4*)&W2[(kc_ + k0_) * EMBn + c40]; \
            int q1_ = q0_ + 1;                                                                \
            int k1_ = q1_ >> 4, c41 = (q1_ & 15) * 4;                                         \
            *(float4*)&fs->sB[buf][k1_][c41] = *(const float4*)&W2[(kc_ + k1_) * EMBn + c41]; \
        }

        BUILD_CHUNK(0, 0)
        __syncthreads();

        for (int c = 0; c < 32; c++) {
            int cur = c & 1;
            if (c + 1 < 32) BUILD_CHUNK(c + 1, (c + 1) & 1)
            #pragma unroll
            for (int kk = 0; kk < 32; kk++) {
                float4 b = *(const float4*)&fs->sB[cur][kk][tx * 4];
                float2 b01 = make_float2(b.x, b.y);
                float2 b23 = make_float2(b.z, b.w);
                float4 A01 = *(const float4*)&fs->sAt[cur][kk][ty * 4];
                float4 A23 = *(const float4*)&fs->sAt[cur][kk][ty * 4 + 2];
                float2 a0 = make_float2(A01.x, A01.y);
                float2 a1 = make_float2(A01.z, A01.w);
                float2 a2 = make_float2(A23.x, A23.y);
                float2 a3 = make_float2(A23.z, A23.w);
                acc[0][0] = ffma2(a0, b01, acc[0][0]); acc[0][1] = ffma2(a0, b23, acc[0][1]);
                acc[1][0] = ffma2(a1, b01, acc[1][0]); acc[1][1] = ffma2(a1, b23, acc[1][1]);
                acc[2][0] = ffma2(a2, b01, acc[2][0]); acc[2][1] = ffma2(a2, b23, acc[2][1]);
                acc[3][0] = ffma2(a3, b01, acc[3][0]); acc[3][1] = ffma2(a3, b23, acc[3][1]);
            }
            __syncthreads();
        }

        #pragma unroll
        for (int i = 0; i < 4; i++) {
            int r = row0 + ty * 4 + i;
            g_h2[r * EMBn + tx * 4 + 0] = acc[i][0].x;
            g_h2[r * EMBn + tx * 4 + 1] = acc[i][0].y;
            g_h2[r * EMBn + tx * 4 + 2] = acc[i][1].x;
            g_h2[r * EMBn + tx * 4 + 3] = acc[i][1].y;
        }
        float4 a_s = *(const float4*)&as2[tx * 4];
        float4 a_d = *(const float4*)&ad2[tx * 4];
        #pragma unroll
        for (int i = 0; i < 4; i++) {
            float ss = acc[i][0].x * a_s.x + acc[i][0].y * a_s.y + acc[i][1].x * a_s.z + acc[i][1].y * a_s.w;
            float sd = acc[i][0].x * a_d.x + acc[i][0].y * a_d.y + acc[i][1].x * a_d.z + acc[i][1].y * a_d.w;
            #pragma unroll
            for (int o = 1; o < 16; o <<= 1) {
                ss += __shfl_xor_sync(0xffffffffu, ss, o);
                sd += __shfl_xor_sync(0xffffffffu, sd, o);
            }
            if (tx == 0) {
                g_a2s[row0 + ty * 4 + i] = ss;
                g_a2d[row0 + ty * 4 + i] = sd;
            }
        }
    }
    gbar();

    // ================= phase 4: conv2 softmax-agg =================
    {
        Conv2S* cs = (Conv2S*)pool;
        int lane = tid & 31;
        int w = (tid >> 5) & 7;
        int wg = gidx >> 5;                     // global warp id, 2368 warps
        // heavy half: warp per dst, grid-stride
        for (int d = NLOW + wg; d < NT; d += NBLK * 8) {
            int deg = g_cursor[d];
            const int* bkt = g_bucket + d * BCAP;
            float adv = g_a2d[d];
            float se = 0.f;
            for (int e = lane; e < deg; e += 32) {
                int s = bkt[e];
                float ea = __expf(leaky(g_a2s[s] + adv));
                cs->wbuf[w][e] = ea;
                cs->ibuf[w][e] = s;
                se += ea;
            }
            __syncwarp();
            float2 acc = make_float2(0.f, 0.f);
            #pragma unroll 4
            for (int e = 0; e < deg; e++) {
                float ea = cs->wbuf[w][e];
                int s = cs->ibuf[w][e];
                float2 v = ((const float2*)(g_h2 + s * 64))[lane];
                acc.x = fmaf(ea, v.x, acc.x);
                acc.y = fmaf(ea, v.y, acc.y);
            }
            __syncwarp();
            se = warp_sum(se);
            float inv = 1.0f / se;
            float2 bb = ((const float2*)b2)[lane];
            int b = d / Nn, n = d - b * Nn;
            int c = lane * 2;
            g_x2t[(n * 64 + c) * 16 + b]     = elu(acc.x * inv + bb.x);
            g_x2t[(n * 64 + c + 1) * 16 + b] = elu(acc.y * inv + bb.y);
        }
        // low half: pure elementwise elu(h2 + b2)
        for (int i = gidx; i < NLOW * 32; i += NTOT) {
            int d = i >> 5, ln = i & 31;
            float2 v = ((const float2*)(g_h2 + d * 64))[ln];
            float2 bb = ((const float2*)b2)[ln];
            int b = d / Nn, n = d - b * Nn;
            int c = ln * 2;
            g_x2t[(n * 64 + c) * 16 + b]     = elu(v.x + bb.x);
            g_x2t[(n * 64 + c + 1) * 16 + b] = elu(v.y + bb.y);
        }
    }
    gbar();

    // ================= phase 5: mlp1 split-K stage 1 (+ cursor reset) =================
    {
        if (gidx < NT) g_cursor[gidx] = 0;      // reset buckets for next replay
        Mlp1S* ms = (Mlp1S*)pool;
        int half = tid >> 7;
        int j = tid & 127;
        int g = bid * 2 + half;
        float* sx = ms->sx[half];
        float4* sx4 = (float4*)sx;
        if (g < NCHUNK) {
            int k0 = g * CK;
            const float4* gx4 = (const float4*)(g_x2t + k0 * 16);
            #pragma unroll
            for (int i = 0; i < 5; i++)
                sx4[j + i * 128] = gx4[j + i * 128];
        }
        __syncthreads();
        if (g < NCHUNK) {
            int k0 = g * CK;
            float2 acc[8];
            #pragma unroll
            for (int p = 0; p < 8; p++) acc[p] = make_float2(0.f, 0.f);
            #pragma unroll 2
            for (int k = 0; k < CK; k++) {
                float wv = mw1[(k0 + k) * HIDn + j];
                float2 w2 = make_float2(wv, wv);
                float4 x0 = sx4[k * 4 + 0];
                float4 x1 = sx4[k * 4 + 1];
                float4 x2 = sx4[k * 4 + 2];
                float4 x3 = sx4[k * 4 + 3];
                acc[0] = ffma2(make_float2(x0.x, x0.y), w2, acc[0]);
                acc[1] = ffma2(make_float2(x0.z, x0.w), w2, acc[1]);
                acc[2] = ffma2(make_float2(x1.x, x1.y), w2, acc[2]);
                acc[3] = ffma2(make_float2(x1.z, x1.w), w2, acc[3]);
                acc[4] = ffma2(make_float2(x2.x, x2.y), w2, acc[4]);
                acc[5] = ffma2(make_float2(x2.z, x2.w), w2, acc[5]);
                acc[6] = ffma2(make_float2(x3.x, x3.y), w2, acc[6]);
                acc[7] = ffma2(make_float2(x3.z, x3.w), w2, acc[7]);
            }
            #pragma unroll
            for (int p = 0; p < 8; p++) {
                g_part[(g * 16 + 2 * p) * HIDn + j]     = acc[p].x;
                g_part[(g * 16 + 2 * p + 1) * HIDn + j] = acc[p].y;
            }
        }
    }
    gbar();

    // ================= phase 6: mlp1 reduce =================
    if (gidx < 16 * HIDn) {
        int b = gidx >> 7, j = gidx & 127;
        float s = 0.f;
        #pragma unroll 4
        for (int c = 0; c < NCHUNK; c++)
            s += g_part[(c * 16 + b) * HIDn + j];
        s += mb1[j];
        g_y1[b * HIDn + j] = fmaxf(s, 0.f);
    }
    gbar();

    // ================= phase 7: mlp2 =================
    if (bid == 0) {
        TailS* ts = (TailS*)pool;
        for (int i = tid; i < 16 * HIDn; i += NTHR) ts->ys[i] = g_y1[i];
        __syncthreads();
        if (tid < 128) {
            int j = tid;
            float acc[16];
            #pragma unroll
            for (int b = 0; b < 16; b++) acc[b] = 0.f;
            #pragma unroll 4
            for (int k = 0; k < HIDn; k++) {
                float wv = mw2[k * HIDn + j];
                #pragma unroll
                for (int b = 0; b < 16; b++)
                    acc[b] = fmaf(ts->ys[b * HIDn + k], wv, acc[b]);
            }
            #pragma unroll
            for (int b = 0; b < 16; b++)
                g_y2[b * HIDn + j] = fmaxf(acc[b] + mb2[j], 0.f);
        }
    }
    gbar();

    // ================= phase 8: output head =================
    if (bid < 8) {
        TailS* ts = (TailS*)pool;
        for (int i = tid; i < 16 * HIDn; i += NTHR) ts->ys[i] = g_y2[i];
        __syncthreads();
        int j = bid * 128 + (tid & 127);
        int bh = tid >> 7;
        if (j < Nn) {
            float acc[8];
            #pragma unroll
            for (int b = 0; b < 8; b++) acc[b] = 0.f;
            const float* y = ts->ys + bh * 8 * HIDn;
            #pragma unroll 4
            for (int k = 0; k < HIDn; k++) {
                float wv = ow[k * Nn + j];
                #pragma unroll
                for (int b = 0; b < 8; b++)
                    acc[b] = fmaf(y[b * HIDn + k], wv, acc[b]);
            }
            float obj = ob[j];
            #pragma unroll
            for (int b = 0; b < 8; b++) {
                float v = acc[b] + obj;
                out[(bh * 8 + b) * Nn + j] = 1.0f / (1.0f + __expf(-v));
            }
        }
    }
}

// ------------------------- launch -------------------------
extern "C" void kernel_launch(void* const* d_in, const int* in_sizes, int n_in,
                              void* d_out, int out_size) {
    const float* actions = (const float*)d_in[0];
    const float* nodef   = (const float*)d_in[1];
    const int*   ei      = (const int*)d_in[2];
    const float* W1  = (const float*)d_in[3];
    const float* as1 = (const float*)d_in[4];
    const float* ad1 = (const float*)d_in[5];
    const float* b1  = (const float*)d_in[6];
    const float* W2  = (const float*)d_in[7];
    const float* as2 = (const float*)d_in[8];
    const float* ad2 = (const float*)d_in[9];
    const float* b2  = (const float*)d_in[10];
    const float* mw1 = (const float*)d_in[11];
    const float* mb1 = (const float*)d_in[12];
    const float* mw2 = (const float*)d_in[13];
    const float* mb2 = (const float*)d_in[14];
    const float* ow  = (const float*)d_in[15];
    const float* ob  = (const float*)d_in[16];
    float* out = (float*)d_out;

    fused_kernel<<<NBLK, NTHR>>>(actions, nodef, ei, W1, as1, ad1, b1,
                                 W2, as2, ad2, b2, mw1, mb1, mw2, mb2, ow, ob, out);
}

// round 9
// speedup vs baseline: 1.0028x; 1.0028x over previous
#include <cuda_runtime.h>
#include <math.h>

#define Bn 16
#define Nn 1000
#define En 16000
#define NT 16000          /* Bn*Nn total nodes  */
#define EBASE 256000      /* Bn*En edges before self loops */
#define ETOT 272000       /* + NT self loops */
#define TWOE 32000
#define HALFB 8
#define NLOW 8000         /* dsts 0..7999 have only their self loop (structural) */

#define H1n 8
#define F1 1024           /* H1*C1 */
#define EMBn 64
#define HIDn 128
#define BCAP 96           /* bucket capacity per heavy dst */

#define NCHUNK 400
#define CK 160            /* 400*160 = 64000 */

#define NBLK 296
#define NTHR 256
#define NTOT (NBLK * NTHR)   /* 75776 threads */

// ------------------------- scratch (static, no allocs) -------------------------
__device__ __align__(16) float4 g_xf[NT];
__device__ float g_psrc[24];
__device__ float g_pdst[24];
__device__ int   g_cursor[NT];                       // zero at load; re-zeroed in mlp1 phase
__device__ int   g_bucket[NT * BCAP];
__device__ __align__(16) float g_s[NT * 24];
__device__ __align__(16) float g_h2[NT * EMBn];
__device__ float g_a2s[NT];
__device__ float g_a2d[NT];
__device__ __align__(16) float g_x2t[64000 * 16];
__device__ float g_part[NCHUNK * 16 * HIDn];
__device__ float g_y1[16 * HIDn];
__device__ unsigned g_bar_count;
__device__ unsigned g_bar_gen;

// ------------------------- helpers -------------------------
__device__ __forceinline__ void edge_sd(int e, const int* __restrict__ EI, int& src, int& dst) {
    if (e < EBASE) {
        int b   = e / TWOE;
        int rem = e - b * TWOE;
        src = EI[b * TWOE + rem] + b * Nn;
        int b2 = b + HALFB;
        dst = EI[b2 * TWOE + rem] + b2 * Nn;
    } else {
        src = dst = e - EBASE;
    }
}

__device__ __forceinline__ float warp_sum(float v) {
    #pragma unroll
    for (int o = 16; o > 0; o >>= 1) v += __shfl_xor_sync(0xffffffffu, v, o);
    return v;
}
__device__ __forceinline__ float leaky(float v) { return v > 0.f ? v : 0.2f * v; }
__device__ __forceinline__ float elu(float v)   { return v > 0.f ? v : (__expf(v) - 1.0f); }

__device__ __forceinline__ float2 ffma2(float2 a, float2 b, float2 c) {
    unsigned long long A = *reinterpret_cast<unsigned long long*>(&a);
    unsigned long long B = *reinterpret_cast<unsigned long long*>(&b);
    unsigned long long C = *reinterpret_cast<unsigned long long*>(&c);
    unsigned long long D;
    asm("fma.rn.f32x2 %0, %1, %2, %3;" : "=l"(D) : "l"(A), "l"(B), "l"(C));
    return *reinterpret_cast<float2*>(&D);
}

// grid barrier (gpu-scope fences flush L1D so cross-SM writes are visible)
__device__ __forceinline__ void gbar() {
    __threadfence();
    __syncthreads();
    if (threadIdx.x == 0) {
        unsigned gen = *(volatile unsigned*)&g_bar_gen;
        if (atomicAdd(&g_bar_count, 1u) == NBLK - 1) {
            g_bar_count = 0;
            __threadfence();
            atomicExch(&g_bar_gen, gen + 1);
        } else {
            while (*(volatile unsigned*)&g_bar_gen == gen) { __nanosleep(32); }
        }
    }
    __syncthreads();
    __threadfence();
}

// ------------------------- shared pool overlays -------------------------
struct P3S {                       // broadcast-GEMM phase: 61,952 B
    float4 w1t[F1];                // 16,384  {W1row0, W1row1, W1row2, b1} per col
    float  w2c[128][EMBn];         // 32,768  W2 chunk (also reused as reduce scratch)
    float  sS[128 * 24];           // 12,288  s rows for this block
    float  satt[128];              //     512 as2 | ad2
};
struct Conv2S {
    float wbuf[8][BCAP];
    int   ibuf[8][BCAP];
};
struct Mlp1S {
    float sx[2][CK * 16];          // 20,480
};
struct TailS {
    float y1s[16 * HIDn];          // 8,192
    float y2s[16 * HIDn];          // 8,192
};

// ------------------------- the one kernel -------------------------
__global__ __launch_bounds__(NTHR, 2) void fused_kernel(
    const float* __restrict__ actions, const float* __restrict__ nodef,
    const int* __restrict__ EI,
    const float* __restrict__ W1, const float* __restrict__ as1,
    const float* __restrict__ ad1, const float* __restrict__ b1,
    const float* __restrict__ W2, const float* __restrict__ as2,
    const float* __restrict__ ad2, const float* __restrict__ b2,
    const float* __restrict__ mw1, const float* __restrict__ mb1,
    const float* __restrict__ mw2, const float* __restrict__ mb2,
    const float* __restrict__ ow,  const float* __restrict__ ob,
    float* __restrict__ out)
{
    __shared__ __align__(16) char pool[sizeof(P3S)];
    int tid = threadIdx.x;
    int bid = blockIdx.x;
    int gidx = bid * NTHR + tid;

    // ================= phase 1: node features + projections + bucket scatter =================
    if (gidx < NT) {
        float ax = actions[gidx * 2 + 0];
        float ay = actions[gidx * 2 + 1];
        float nf = nodef[gidx];
        g_xf[gidx] = make_float4(ax, ay, nf, 0.f);
    } else if (gidx < NT + 48) {
        int t = gidx - NT;
        int which = t / 24;
        int r = t % 24;
        int k = r / 8, h = r % 8;
        const float* att = which ? ad1 : as1;
        float s = 0.f;
        for (int c = 0; c < 128; c++)
            s += W1[k * F1 + h * 128 + c] * att[h * 128 + c];
        (which ? g_pdst : g_psrc)[k * 8 + h] = s;
    }
    #pragma unroll
    for (int q = 0; q < 4; q++) {
        int e = gidx * 4 + q;
        if (e < ETOT) {
            int src, dst;
            edge_sd(e, EI, src, dst);
            if (dst >= NLOW) {
                int pos = atomicAdd(&g_cursor[dst], 1);
                g_bucket[dst * BCAP + pos] = src;
            }
        }
    }
    gbar();

    // ================= phase 2: conv1 attention =================
    if (gidx < 8000) {
        // low half: softmax of single self loop -> s = x[d] replicated across 8 heads
        int d = gidx;
        float4 x = g_xf[d];
        float4 v0 = make_float4(x.x, x.y, x.z, x.x);
        float4 v1 = make_float4(x.y, x.z, x.x, x.y);
        float4 v2 = make_float4(x.z, x.x, x.y, x.z);
        float4* sp = (float4*)(g_s + d * 24);
        sp[0] = v0; sp[1] = v1; sp[2] = v2;
        sp[3] = v0; sp[4] = v1; sp[5] = v2;
    } else if (gidx < 8000 + 64000) {
        int i2 = gidx - 8000;
        int d = NLOW + (i2 >> 3), h = i2 & 7;
        float4 xd = g_xf[d];
        float p0 = g_psrc[h], p1 = g_psrc[8 + h], p2 = g_psrc[16 + h];
        float q0 = g_pdst[h], q1 = g_pdst[8 + h], q2 = g_pdst[16 + h];
        float adv = fmaf(xd.x, q0, fmaf(xd.y, q1, xd.z * q2));
        int deg = g_cursor[d];
        const int* bkt = g_bucket + d * BCAP;
        float se = 0.f, sx = 0.f, sy = 0.f, sz = 0.f;
        for (int e = 0; e < deg; e++) {
            int s = bkt[e];
            float4 x = g_xf[s];
            float a = fmaf(x.x, p0, fmaf(x.y, p1, x.z * p2)) + adv;
            float ea = __expf(leaky(a));
            se += ea;
            sx = fmaf(ea, x.x, sx);
            sy = fmaf(ea, x.y, sy);
            sz = fmaf(ea, x.z, sz);
        }
        float inv = 1.0f / se;
        float* sp = g_s + d * 24 + h * 3;
        sp[0] = sx * inv; sp[1] = sy * inv; sp[2] = sz * inv;
    }
    gbar();

    // ================= phase 3: broadcast-GEMM  h2 = elu(s@W1+b1) @ W2  + attn2 =================
    if (bid < 148) {
        P3S* ps = (P3S*)pool;
        int nrows = 108 + (bid < 16);
        int base = bid * 108 + min(bid, 16);
        int half = tid >> 7;           // warp-uniform: warps 0-3 -> cols 0-31, warps 4-7 -> 32-63
        int slot = tid & 127;
        int row = base + slot;
        bool active = slot < nrows;

        for (int k = tid; k < F1; k += NTHR)
            ps->w1t[k] = make_float4(W1[k], W1[F1 + k], W1[2 * F1 + k], b1[k]);
        for (int i = tid; i < nrows * 24; i += NTHR)
            ps->sS[i] = g_s[base * 24 + i];
        if (tid < 128) ps->satt[tid] = (tid < 64) ? as2[tid] : ad2[tid - 64];

        float2 acc[16];
        #pragma unroll
        for (int j = 0; j < 16; j++) acc[j] = make_float2(0.f, 0.f);

        for (int ch = 0; ch < 8; ch++) {
            __syncthreads();
            {   // load W2 chunk: 128 k-rows x 64 cols = 2048 float4
                const float4* w2g = (const float4*)(W2 + ch * 128 * EMBn);
                float4* w2s = (float4*)ps->w2c;
                #pragma unroll
                for (int i = 0; i < 8; i++)
                    w2s[tid + i * NTHR] = w2g[tid + i * NTHR];
            }
            __syncthreads();
            float s0 = 0.f, s1 = 0.f, s2 = 0.f;
            if (active) {                      // head == chunk (128 cols per head)
                s0 = ps->sS[slot * 24 + ch * 3 + 0];
                s1 = ps->sS[slot * 24 + ch * 3 + 1];
                s2 = ps->sS[slot * 24 + ch * 3 + 2];
            }
            for (int k = 0; k < 128; k++) {
                float4 w = ps->w1t[ch * 128 + k];              // broadcast
                float x1 = fmaf(s0, w.x, fmaf(s1, w.y, fmaf(s2, w.z, w.w)));
                x1 = elu(x1);
                float2 xx = make_float2(x1, x1);
                const float4* brow = (const float4*)&ps->w2c[k][half * 32];  // broadcast
                #pragma unroll
                for (int j = 0; j < 8; j++) {
                    float4 b = brow[j];
                    acc[j * 2]     = ffma2(xx, make_float2(b.x, b.y), acc[j * 2]);
                    acc[j * 2 + 1] = ffma2(xx, make_float2(b.z, b.w), acc[j * 2 + 1]);
                }
            }
        }
        // store h2 (32 cols per thread)
        if (active) {
            float4* dst = (float4*)(g_h2 + row * 64 + half * 32);
            const float4* a4 = (const float4*)acc;
            #pragma unroll
            for (int j = 0; j < 8; j++) dst[j] = a4[j];
        }
        // attn2 partials, combined across halves via smem
        float ss = 0.f, sd = 0.f;
        {
            const float* av = (const float*)acc;
            #pragma unroll
            for (int j = 0; j < 32; j++) {
                float v = av[j];
                ss = fmaf(v, ps->satt[half * 32 + j], ss);
                sd = fmaf(v, ps->satt[64 + half * 32 + j], sd);
            }
        }
        __syncthreads();                       // w2c no longer needed
        float* red = ps->w2c[0];
        red[tid] = ss; red[256 + tid] = sd;
        __syncthreads();
        if (half == 0 && active) {
            g_a2s[row] = red[tid] + red[tid + 128];
            g_a2d[row] = red[256 + tid] + red[256 + tid + 128];
        }
    }
    gbar();

    // ================= phase 4: conv2 softmax-agg =================
    {
        Conv2S* cs = (Conv2S*)pool;
        int lane = tid & 31;
        int w = (tid >> 5) & 7;
        int wg = gidx >> 5;
        for (int d = NLOW + wg; d < NT; d += NBLK * 8) {
            int deg = g_cursor[d];
            const int* bkt = g_bucket + d * BCAP;
            float adv = g_a2d[d];
            float se = 0.f;
            for (int e = lane; e < deg; e += 32) {
                int s = bkt[e];
                float ea = __expf(leaky(g_a2s[s] + adv));
                cs->wbuf[w][e] = ea;
                cs->ibuf[w][e] = s;
                se += ea;
            }
            __syncwarp();
            float2 acc = make_float2(0.f, 0.f);
            #pragma unroll 4
            for (int e = 0; e < deg; e++) {
                float ea = cs->wbuf[w][e];
                int s = cs->ibuf[w][e];
                float2 v = ((const float2*)(g_h2 + s * 64))[lane];
                acc.x = fmaf(ea, v.x, acc.x);
                acc.y = fmaf(ea, v.y, acc.y);
            }
            __syncwarp();
            se = warp_sum(se);
            float inv = 1.0f / se;
            float2 bb = ((const float2*)b2)[lane];
            int b = d / Nn, n = d - b * Nn;
            int c = lane * 2;
            g_x2t[(n * 64 + c) * 16 + b]     = elu(acc.x * inv + bb.x);
            g_x2t[(n * 64 + c + 1) * 16 + b] = elu(acc.y * inv + bb.y);
        }
        for (int i = gidx; i < NLOW * 32; i += NTOT) {
            int d = i >> 5, ln = i & 31;
            float2 v = ((const float2*)(g_h2 + d * 64))[ln];
            float2 bb = ((const float2*)b2)[ln];
            int b = d / Nn, n = d - b * Nn;
            int c = ln * 2;
            g_x2t[(n * 64 + c) * 16 + b]     = elu(v.x + bb.x);
            g_x2t[(n * 64 + c + 1) * 16 + b] = elu(v.y + bb.y);
        }
    }
    gbar();

    // ================= phase 5: mlp1 split-K stage 1 (+ cursor reset) =================
    {
        if (gidx < NT) g_cursor[gidx] = 0;
        Mlp1S* ms = (Mlp1S*)pool;
        int half = tid >> 7;
        int j = tid & 127;
        int g = bid * 2 + half;
        float* sx = ms->sx[half];
        float4* sx4 = (float4*)sx;
        if (g < NCHUNK) {
            int k0 = g * CK;
            const float4* gx4 = (const float4*)(g_x2t + k0 * 16);
            #pragma unroll
            for (int i = 0; i < 5; i++)
                sx4[j + i * 128] = gx4[j + i * 128];
        }
        __syncthreads();
        if (g < NCHUNK) {
            int k0 = g * CK;
            float2 acc[8];
            #pragma unroll
            for (int p = 0; p < 8; p++) acc[p] = make_float2(0.f, 0.f);
            #pragma unroll 2
            for (int k = 0; k < CK; k++) {
                float wv = mw1[(k0 + k) * HIDn + j];
                float2 w2v = make_float2(wv, wv);
                float4 x0 = sx4[k * 4 + 0];
                float4 x1 = sx4[k * 4 + 1];
                float4 x2 = sx4[k * 4 + 2];
                float4 x3 = sx4[k * 4 + 3];
                acc[0] = ffma2(make_float2(x0.x, x0.y), w2v, acc[0]);
                acc[1] = ffma2(make_float2(x0.z, x0.w), w2v, acc[1]);
                acc[2] = ffma2(make_float2(x1.x, x1.y), w2v, acc[2]);
                acc[3] = ffma2(make_float2(x1.z, x1.w), w2v, acc[3]);
                acc[4] = ffma2(make_float2(x2.x, x2.y), w2v, acc[4]);
                acc[5] = ffma2(make_float2(x2.z, x2.w), w2v, acc[5]);
                acc[6] = ffma2(make_float2(x3.x, x3.y), w2v, acc[6]);
                acc[7] = ffma2(make_float2(x3.z, x3.w), w2v, acc[7]);
            }
            #pragma unroll
            for (int p = 0; p < 8; p++) {
                g_part[(g * 16 + 2 * p) * HIDn + j]     = acc[p].x;
                g_part[(g * 16 + 2 * p + 1) * HIDn + j] = acc[p].y;
            }
        }
    }
    gbar();

    // ================= phase 6: mlp1 reduce =================
    if (gidx < 16 * HIDn) {
        int b = gidx >> 7, j = gidx & 127;
        float s = 0.f;
        #pragma unroll 4
        for (int c = 0; c < NCHUNK; c++)
            s += g_part[(c * 16 + b) * HIDn + j];
        s += mb1[j];
        g_y1[b * HIDn + j] = fmaxf(s, 0.f);
    }
    gbar();

    // ================= phase 7: mlp2 (redundant per block) + output head =================
    if (bid < 8) {
        TailS* ts = (TailS*)pool;
        for (int i = tid; i < 16 * HIDn; i += NTHR) ts->y1s[i] = g_y1[i];
        __syncthreads();
        if (tid < 128) {
            int j = tid;
            float acc[16];
            #pragma unroll
            for (int b = 0; b < 16; b++) acc[b] = 0.f;
            #pragma unroll 4
            for (int k = 0; k < HIDn; k++) {
                float wv = mw2[k * HIDn + j];
                #pragma unroll
                for (int b = 0; b < 16; b++)
                    acc[b] = fmaf(ts->y1s[b * HIDn + k], wv, acc[b]);
            }
            #pragma unroll
            for (int b = 0; b < 16; b++)
                ts->y2s[b * HIDn + j] = fmaxf(acc[b] + mb2[j], 0.f);
        }
        __syncthreads();
        int j = bid * 128 + (tid & 127);
        int bh = tid >> 7;
        if (j < Nn) {
            float acc[8];
            #pragma unroll
            for (int b = 0; b < 8; b++) acc[b] = 0.f;
            const float* y = ts->y2s + bh * 8 * HIDn;
            #pragma unroll 4
            for (int k = 0; k < HIDn; k++) {
                float wv = ow[k * Nn + j];
                #pragma unroll
                for (int b = 0; b < 8; b++)
                    acc[b] = fmaf(y[b * HIDn + k], wv, acc[b]);
            }
            float obj = ob[j];
            #pragma unroll
            for (int b = 0; b < 8; b++) {
                float v = acc[b] + obj;
                out[(bh * 8 + b) * Nn + j] = 1.0f / (1.0f + __expf(-v));
            }
        }
    }
}

// ------------------------- launch -------------------------
extern "C" void kernel_launch(void* const* d_in, const int* in_sizes, int n_in,
                              void* d_out, int out_size) {
    const float* actions = (const float*)d_in[0];
    const float* nodef   = (const float*)d_in[1];
    const int*   ei      = (const int*)d_in[2];
    const float* W1  = (const float*)d_in[3];
    const float* as1 = (const float*)d_in[4];
    const float* ad1 = (const float*)d_in[5];
    const float* b1  = (const float*)d_in[6];
    const float* W2  = (const float*)d_in[7];
    const float* as2 = (const float*)d_in[8];
    const float* ad2 = (const float*)d_in[9];
    const float* b2  = (const float*)d_in[10];
    const float* mw1 = (const float*)d_in[11];
    const float* mb1 = (const float*)d_in[12];
    const float* mw2 = (const float*)d_in[13];
    const float* mb2 = (const float*)d_in[14];
    const float* ow  = (const float*)d_in[15];
    const float* ob  = (const float*)d_in[16];
    float* out = (float*)d_out;

    fused_kernel<<<NBLK, NTHR>>>(actions, nodef, ei, W1, as1, ad1, b1,
                                 W2, as2, ad2, b2, mw1, mb1, mw2, mb2, ow, ob, out);
}